// round 9
// baseline (speedup 1.0000x reference)
#include <cuda_runtime.h>
#include <cuda_bf16.h>

#define T_SEQ   256
#define HID     128
#define BATCH   1024
#define VOCABN  60
#define NCTA    152

#define FMA2(acc, a, b) \
    asm("fma.rn.f32x2 %0, %1, %2, %0;" : "+l"(acc) : "l"(a), "l"(b))
#define ADD2(dst, a, b) \
    asm("add.rn.f32x2 %0, %1, %2;" : "=l"(dst) : "l"(a), "l"(b))
#define UNPACK2(lo, hi, v) \
    asm("mov.b64 {%0,%1}, %2;" : "=f"(lo), "=f"(hi) : "l"(v))

__device__ __forceinline__ float tanh_fast(float z) {
    float e = __expf(2.0f * z);
    return 1.0f - __fdividef(2.0f, e + 1.0f);
}

// ============ single fused kernel: sort + P + RNN + FC ============
// 152 CTAs x 256 threads (2 groups of 128; per-SMSP one warp of each group).
// Every CTA runs an identical DETERMINISTIC counting sort (match/popc ranks,
// no atomics) -> identical permutation everywhere.
// Work unit = DUAL (2 sorted-adjacent rows) per group slot; 232 longest duals
// run alone, 280 shortest packed 4-per-slot (balanced quadruples, ~281 steps).
// Thread j holds W row j as 64 packed f32x2 regs; h via broadcast LDS.128.
// FC (60-col) computed in-group at dual completion from retired h.
__global__ __launch_bounds__(256, 1) void rnn_all(
    const int* __restrict__ x, const int* __restrict__ lengths,
    const float* __restrict__ W_hh,
    const float* __restrict__ emb, const float* __restrict__ W_ih,
    const float* __restrict__ W_fc, const float* __restrict__ b_fc,
    float* __restrict__ out)
{
    // aliased scratch: sort phase then main phase
    __shared__ __align__(16) unsigned char raw[38912];
    __shared__ __align__(16) float sh_h[2][2][2][HID];   // [g][s][buf][j] 4 KB

    int* hist = (int*)raw;              // [32][256] per-block bin counts -> excl offsets
    int* tot  = (int*)(raw + 32768);    // [256]
    int* bse  = (int*)(raw + 33792);    // [256] exclusive bin base
    int* perm = (int*)(raw + 34816);    // [1024]
    float* shP          = (float*)raw;                 // [60*128] (after sort)
    unsigned char* stok = raw + 30720;                 // [2][2][256]
    float* sret         = (float*)(raw + 31744);       // [2][2][128] retired h

    int tid  = threadIdx.x;
    int g    = tid >> 7;
    int j    = tid & 127;
    int lane = tid & 31;
    int wrp  = tid >> 5;
    int c    = blockIdx.x;

    // ---------- deterministic counting sort (no atomics) ----------
    for (int i = tid; i < 8192; i += 256) hist[i] = 0;
    __syncthreads();
    int myintra[4], mylen[4];
#pragma unroll
    for (int bi = 0; bi < 4; bi++) {
        int b = wrp + bi * 8;                 // block of 32 rows
        int r = b * 32 + lane;
        int l = lengths[r] - 1;               // bin 0..255
        unsigned mask = __match_any_sync(0xffffffffu, l);
        int intra = __popc(mask & ((1u << lane) - 1u));
        if (intra == 0) hist[b * 256 + l] = __popc(mask);
        myintra[bi] = intra; mylen[bi] = l;
    }
    __syncthreads();
    {   // per-bin serial scan over 32 blocks (thread == bin)
        int run = 0;
#pragma unroll
        for (int b = 0; b < 32; b++) {
            int v = hist[b * 256 + tid];
            hist[b * 256 + tid] = run;
            run += v;
        }
        tot[tid] = run;
    }
    __syncthreads();
    {   // exclusive scan over 256 bins (Hillis-Steele, deterministic)
        int v = tot[tid];
        bse[tid] = v;
        __syncthreads();
        for (int d = 1; d < 256; d <<= 1) {
            int o = (tid >= d) ? bse[tid - d] : 0;
            __syncthreads();
            v += o; bse[tid] = v;
            __syncthreads();
        }
        int e = (tid > 0) ? bse[tid - 1] : 0;
        __syncthreads();
        bse[tid] = e;
    }
    __syncthreads();
#pragma unroll
    for (int bi = 0; bi < 4; bi++) {
        int b = wrp + bi * 8;
        int r = b * 32 + lane;
        int l = mylen[bi];
        perm[bse[l] + hist[b * 256 + l] + myintra[bi]] = r;
    }
    __syncthreads();

    // ---------- slot assignment ----------
    // slot q = c + 152*g in [0,303]. q<232: single dual (511-q).
    // q>=232: sl=q-232<70: quadruple {sl,139-sl,140+sl,279-sl} (sum~281 steps).
    int q = c + 152 * g;
    int nd = 0, dl[4];
    if (q < 232) { nd = 1; dl[0] = 511 - q; }
    else {
        int sl = q - 232;
        if (sl < 70) { nd = 4; dl[0] = sl; dl[1] = 139 - sl; dl[2] = 140 + sl; dl[3] = 279 - sl; }
    }
    int rows[8];
#pragma unroll
    for (int k = 0; k < 4; k++) {
        if (k < nd) { rows[2*k] = perm[2*dl[k]]; rows[2*k+1] = perm[2*dl[k]+1]; }
    }
    __syncthreads();   // all perm reads done; raw is now reusable

    // ---------- stage emb, compute P = emb @ W_ih^T in place ----------
    for (int i = tid; i < VOCABN * HID; i += 256) shP[i] = emb[i];
    unsigned long long w[64];
    {
        const ulonglong2* Wq = reinterpret_cast<const ulonglong2*>(W_ih) + (size_t)j * 32;
#pragma unroll
        for (int i = 0; i < 32; i++) { ulonglong2 tq = Wq[i]; w[2*i] = tq.x; w[2*i+1] = tq.y; }
    }
    __syncthreads();
#pragma unroll 1
    for (int wave = 0; wave < 2; wave++) {
        float pv[15];
        int v0 = g * 30 + wave * 15;
#pragma unroll 1
        for (int vi = 0; vi < 15; vi++) {
            const ulonglong2* eq = reinterpret_cast<const ulonglong2*>(&shP[(v0 + vi) * HID]);
            unsigned long long a0 = 0ull, a1 = 0ull, a2 = 0ull, a3 = 0ull;
#pragma unroll
            for (int i = 0; i < 32; i += 2) {
                ulonglong2 e0 = eq[i];
                ulonglong2 e1 = eq[i + 1];
                FMA2(a0, w[2*i + 0], e0.x);
                FMA2(a1, w[2*i + 1], e0.y);
                FMA2(a2, w[2*i + 2], e1.x);
                FMA2(a3, w[2*i + 3], e1.y);
            }
            ADD2(a0, a0, a1); ADD2(a2, a2, a3); ADD2(a0, a0, a2);
            float lo, hi; UNPACK2(lo, hi, a0);
            pv[vi] = lo + hi;
        }
        __syncthreads();
#pragma unroll
        for (int vi = 0; vi < 15; vi++) shP[(v0 + vi) * HID + j] = pv[vi];
        __syncthreads();
    }
    // reload w <- W_hh row j
    {
        const ulonglong2* Wq = reinterpret_cast<const ulonglong2*>(W_hh) + (size_t)j * 32;
#pragma unroll
        for (int i = 0; i < 32; i++) { ulonglong2 tq = Wq[i]; w[2*i] = tq.x; w[2*i+1] = tq.y; }
    }

    // ---------- duals: RNN recurrence + fused FC ----------
#pragma unroll 1
    for (int k = 0; k < nd; k++) {
        int r0 = rows[2*k], r1 = rows[2*k+1];
        int le0 = lengths[r0] - 1;
        int le1 = lengths[r1] - 1;
        int L = le1 + 1;                         // perm ascending -> r1 longest

        asm volatile("bar.sync %0, 128;" :: "r"(g + 1) : "memory");
        stok[(g*2+0)*T_SEQ + j]       = (unsigned char)x[r0 * T_SEQ + j];
        stok[(g*2+0)*T_SEQ + j + 128] = (unsigned char)x[r0 * T_SEQ + j + 128];
        stok[(g*2+1)*T_SEQ + j]       = (unsigned char)x[r1 * T_SEQ + j];
        stok[(g*2+1)*T_SEQ + j + 128] = (unsigned char)x[r1 * T_SEQ + j + 128];
        sh_h[g][0][0][j] = 0.0f;
        sh_h[g][1][0][j] = 0.0f;
        asm volatile("bar.sync %0, 128;" :: "r"(g + 1) : "memory");

#pragma unroll 1
        for (int t = 0; t < L; t++) {
            int cur = t & 1, nxt = cur ^ 1;
#pragma unroll
            for (int s = 0; s < 2; s++) {
                int tok    = stok[(g*2+s)*T_SEQ + t];
                float base = shP[tok * HID + j];
                const ulonglong2* hq = reinterpret_cast<const ulonglong2*>(&sh_h[g][s][cur][0]);
                unsigned long long a0 = 0ull, a1 = 0ull, a2 = 0ull, a3 = 0ull;
                ulonglong2 b0 = hq[0], b1 = hq[1], b2 = hq[2], b3 = hq[3];
#pragma unroll
                for (int i = 0; i < 32; i += 4) {
                    ulonglong2 n0, n1, n2, n3;
                    if (i + 4 < 32) { n0 = hq[i+4]; n1 = hq[i+5]; n2 = hq[i+6]; n3 = hq[i+7]; }
                    FMA2(a0, w[2*i + 0], b0.x);
                    FMA2(a1, w[2*i + 1], b0.y);
                    FMA2(a2, w[2*i + 2], b1.x);
                    FMA2(a3, w[2*i + 3], b1.y);
                    FMA2(a0, w[2*i + 4], b2.x);
                    FMA2(a1, w[2*i + 5], b2.y);
                    FMA2(a2, w[2*i + 6], b3.x);
                    FMA2(a3, w[2*i + 7], b3.y);
                    b0 = n0; b1 = n1; b2 = n2; b3 = n3;
                }
                ADD2(a0, a0, a1); ADD2(a2, a2, a3); ADD2(a0, a0, a2);
                float lo, hi; UNPACK2(lo, hi, a0);
                float h = tanh_fast(base + lo + hi);
                sh_h[g][s][nxt][j] = h;
                int lend = s ? le1 : le0;
                if (t == lend) sret[(g*2+s)*HID + j] = h;   // retire h for FC
            }
            asm volatile("bar.sync %0, 128;" :: "r"(g + 1) : "memory");
        }

        // fused FC: out[r] = W_fc @ h_ret + b_fc (threads 0..59 of group)
        if (j < VOCABN) {
            const float* wf = W_fc + j * HID;
#pragma unroll
            for (int s = 0; s < 2; s++) {
                const float* hh = sret + (g*2+s)*HID;
                float acc = b_fc[j];
#pragma unroll 16
                for (int k2 = 0; k2 < HID; k2++) acc += wf[k2] * hh[k2];
                int r = s ? r1 : r0;
                out[(size_t)r * VOCABN + j] = acc;
            }
        }
    }
}

// ---------------- launch ----------------
extern "C" void kernel_launch(void* const* d_in, const int* in_sizes, int n_in,
                              void* d_out, int out_size) {
    const int*   x       = (const int*)d_in[0];
    const int*   lengths = (const int*)d_in[1];
    const float* emb     = (const float*)d_in[2];
    const float* W_ih    = (const float*)d_in[3];
    const float* W_hh    = (const float*)d_in[4];
    const float* W_fc    = (const float*)d_in[5];
    const float* b_fc    = (const float*)d_in[6];
    float*       out     = (float*)d_out;

    rnn_all<<<NCTA, 256>>>(x, lengths, W_hh, emb, W_ih, W_fc, b_fc, out);
}

// round 10
// speedup vs baseline: 1.0912x; 1.0912x over previous
#include <cuda_runtime.h>
#include <cuda_bf16.h>

#define T_SEQ   256
#define HID     128
#define BATCH   1024
#define VOCABN  60
#define NCTA    152

#define FMA2(acc, a, b) \
    asm("fma.rn.f32x2 %0, %1, %2, %0;" : "+l"(acc) : "l"(a), "l"(b))
#define ADD2(dst, a, b) \
    asm("add.rn.f32x2 %0, %1, %2;" : "=l"(dst) : "l"(a), "l"(b))
#define UNPACK2(lo, hi, v) \
    asm("mov.b64 {%0,%1}, %2;" : "=f"(lo), "=f"(hi) : "l"(v))

__device__ __forceinline__ float tanh_fast(float z) {
    float e = __expf(2.0f * z);
    return 1.0f - __fdividef(2.0f, e + 1.0f);
}

// 4-output x 32-k register-blocked partial dot:
// src = 32 consecutive floats (8 ulonglong2), w = 4 rows x 32 floats packed.
__device__ __forceinline__ void dot4(
    const ulonglong2* __restrict__ src, const unsigned long long* w,
    float& s0, float& s1, float& s2, float& s3)
{
    unsigned long long vv[16];
#pragma unroll
    for (int i = 0; i < 8; i++) { ulonglong2 t = src[i]; vv[2*i] = t.x; vv[2*i+1] = t.y; }
    unsigned long long A[8];
#pragma unroll
    for (int i = 0; i < 8; i++) A[i] = 0ull;
#pragma unroll
    for (int m = 0; m < 4; m++) {
        const unsigned long long* wm = w + m * 16;
#pragma unroll
        for (int i = 0; i < 16; i += 2) {
            FMA2(A[2*m],     wm[i],     vv[i]);
            FMA2(A[2*m + 1], wm[i + 1], vv[i + 1]);
        }
    }
    float lo, hi;
    ADD2(A[0], A[0], A[1]); UNPACK2(lo, hi, A[0]); s0 = lo + hi;
    ADD2(A[2], A[2], A[3]); UNPACK2(lo, hi, A[2]); s1 = lo + hi;
    ADD2(A[4], A[4], A[5]); UNPACK2(lo, hi, A[4]); s2 = lo + hi;
    ADD2(A[6], A[6], A[7]); UNPACK2(lo, hi, A[6]); s3 = lo + hi;
}

// reduce partials across the lane quad (xor 1, xor 2) and select own output (m == kq)
__device__ __forceinline__ float quad_reduce_sel(float s0, float s1, float s2, float s3, int kq) {
    s0 += __shfl_xor_sync(0xffffffffu, s0, 1); s0 += __shfl_xor_sync(0xffffffffu, s0, 2);
    s1 += __shfl_xor_sync(0xffffffffu, s1, 1); s1 += __shfl_xor_sync(0xffffffffu, s1, 2);
    s2 += __shfl_xor_sync(0xffffffffu, s2, 1); s2 += __shfl_xor_sync(0xffffffffu, s2, 2);
    s3 += __shfl_xor_sync(0xffffffffu, s3, 1); s3 += __shfl_xor_sync(0xffffffffu, s3, 2);
    return (kq & 2) ? ((kq & 1) ? s3 : s2) : ((kq & 1) ? s1 : s0);
}

// load 4x32 weight block for rows j4+32m, k-chunk kq (row = 32 ulonglong2)
__device__ __forceinline__ void load_wblock(
    const float* __restrict__ Wsrc, int j4, int kq, unsigned long long* w)
{
#pragma unroll
    for (int m = 0; m < 4; m++) {
        const ulonglong2* Wq =
            reinterpret_cast<const ulonglong2*>(Wsrc) + (size_t)(j4 + 32*m) * 32 + kq * 8;
#pragma unroll
        for (int i = 0; i < 8; i++) {
            ulonglong2 t = Wq[i];
            w[m*16 + 2*i]     = t.x;
            w[m*16 + 2*i + 1] = t.y;
        }
    }
}

// ============ single fused kernel: sort + P + RNN + FC ============
// 152 CTAs x 256 threads (2 groups of 128). Deterministic counting sort (match/
// popc ranks, no atomics) -> identical permutation in every CTA. Work unit =
// dual of sorted-adjacent rows: 232 longest duals run alone, 280 shortest in 70
// balanced quadruple slots (~281-step critical path).
// GEMV register-blocked R=4 x C=32: thread (j4,kq) holds 4x32 W block in regs,
// reads only its 128B h-chunk (skewed conflict-free layout), quad-shfl reduce.
__global__ __launch_bounds__(256, 1) void rnn_all(
    const int* __restrict__ x, const int* __restrict__ lengths,
    const float* __restrict__ W_hh,
    const float* __restrict__ emb, const float* __restrict__ W_ih,
    const float* __restrict__ W_fc, const float* __restrict__ b_fc,
    float* __restrict__ out)
{
    __shared__ __align__(16) unsigned char raw[34816];
    __shared__ __align__(16) float shH[2][2][2][144];   // [g][slot][buf][4 chunks x 36]

    unsigned short* hist = (unsigned short*)raw;            // [32][256] u16
    int*            tot  = (int*)(raw + 16384);             // [256]
    int*            bse  = (int*)(raw + 17408);             // [256]
    unsigned short* perm = (unsigned short*)(raw + 18432);  // [1024]
    float*          shP  = (float*)raw;                     // [60*128] (after sort)
    unsigned char*  stok = raw + 30720;                     // [4][256]
    float*          sret = (float*)(raw + 31744);           // [4][128]

    int tid  = threadIdx.x;
    int g    = tid >> 7;
    int u    = tid & 127;
    int kq   = u & 3;            // k-chunk 0..3
    int j4   = u >> 2;           // 0..31
    int jown = j4 + 32 * kq;     // owned output index
    int lane = tid & 31;
    int wrp  = tid >> 5;
    int c    = blockIdx.x;

    // ---------- deterministic counting sort ----------
    for (int i = tid; i < 8192; i += 256) hist[i] = 0;
    __syncthreads();
    int myintra[4], mylen[4];
#pragma unroll
    for (int bi = 0; bi < 4; bi++) {
        int b = wrp + bi * 8;
        int r = b * 32 + lane;
        int l = lengths[r] - 1;
        unsigned mask = __match_any_sync(0xffffffffu, l);
        int intra = __popc(mask & ((1u << lane) - 1u));
        if (intra == 0) hist[b * 256 + l] = (unsigned short)__popc(mask);
        myintra[bi] = intra; mylen[bi] = l;
    }
    __syncthreads();
    {   // per-bin serial scan over 32 blocks (thread == bin)
        int run = 0;
#pragma unroll
        for (int b = 0; b < 32; b++) {
            int v = hist[b * 256 + tid];
            hist[b * 256 + tid] = (unsigned short)run;
            run += v;
        }
        tot[tid] = run;
    }
    __syncthreads();
    {   // exclusive scan over 256 bins
        int v = tot[tid];
        bse[tid] = v;
        __syncthreads();
        for (int d = 1; d < 256; d <<= 1) {
            int o = (tid >= d) ? bse[tid - d] : 0;
            __syncthreads();
            v += o; bse[tid] = v;
            __syncthreads();
        }
        int e = (tid > 0) ? bse[tid - 1] : 0;
        __syncthreads();
        bse[tid] = e;
    }
    __syncthreads();
#pragma unroll
    for (int bi = 0; bi < 4; bi++) {
        int b = wrp + bi * 8;
        int r = b * 32 + lane;
        int l = mylen[bi];
        perm[bse[l] + hist[b * 256 + l] + myintra[bi]] = (unsigned short)r;
    }
    __syncthreads();

    // ---------- slot assignment ----------
    int q = c + 152 * g;
    int nd = 0;
    int dls[4] = {0, 0, 0, 0};
    if (q < 232) { nd = 1; dls[0] = 511 - q; }
    else if (q - 232 < 70) {
        int sl = q - 232;
        nd = 4; dls[0] = sl; dls[1] = 139 - sl; dls[2] = 140 + sl; dls[3] = 279 - sl;
    }
    int rows[8], les[8];
#pragma unroll 1
    for (int k = 0; k < nd; k++) {
        int d = dls[k];
        int a = perm[2 * d], b = perm[2 * d + 1];
        rows[2*k] = a;  rows[2*k+1] = b;
        les[2*k] = lengths[a] - 1;  les[2*k+1] = lengths[b] - 1;
    }
    __syncthreads();            // perm reads done; raw reusable

    // ---------- P = emb @ W_ih^T (emb straight from L1) ----------
    unsigned long long w[64];
    load_wblock(W_ih, j4, kq, w);
#pragma unroll 1
    for (int vi = 0; vi < 30; vi++) {
        int v = g * 30 + vi;
        const ulonglong2* eq = reinterpret_cast<const ulonglong2*>(emb + v * HID) + kq * 8;
        float s0, s1, s2, s3;
        dot4(eq, w, s0, s1, s2, s3);
        shP[v * HID + jown] = quad_reduce_sel(s0, s1, s2, s3, kq);
    }
    __syncthreads();

    // ---------- reload w <- W_hh block ----------
    load_wblock(W_hh, j4, kq, w);

    // ---------- duals: RNN recurrence + fused FC ----------
#pragma unroll 1
    for (int k = 0; k < nd; k++) {
        int r0 = rows[2*k], r1 = rows[2*k+1];
        int le0 = les[2*k], le1 = les[2*k+1];
        int L = le1 + 1;                      // perm ascending -> r1 longest

        asm volatile("bar.sync %0, 128;" :: "r"(g + 1) : "memory");
        stok[(2*g + 0) * T_SEQ + u]       = (unsigned char)x[r0 * T_SEQ + u];
        stok[(2*g + 0) * T_SEQ + u + 128] = (unsigned char)x[r0 * T_SEQ + u + 128];
        stok[(2*g + 1) * T_SEQ + u]       = (unsigned char)x[r1 * T_SEQ + u];
        stok[(2*g + 1) * T_SEQ + u + 128] = (unsigned char)x[r1 * T_SEQ + u + 128];
        shH[g][0][0][kq * 36 + j4] = 0.0f;
        shH[g][1][0][kq * 36 + j4] = 0.0f;
        asm volatile("bar.sync %0, 128;" :: "r"(g + 1) : "memory");

#pragma unroll 1
        for (int t = 0; t < L; t++) {
            int cur = t & 1, nxt = cur ^ 1;
#pragma unroll
            for (int s = 0; s < 2; s++) {
                int tok    = stok[(2*g + s) * T_SEQ + t];
                float base = shP[tok * HID + jown];
                const ulonglong2* hq =
                    reinterpret_cast<const ulonglong2*>(&shH[g][s][cur][kq * 36]);
                float s0, s1, s2, s3;
                dot4(hq, w, s0, s1, s2, s3);
                float z = base + quad_reduce_sel(s0, s1, s2, s3, kq);
                float h = tanh_fast(z);
                shH[g][s][nxt][kq * 36 + j4] = h;
                int lend = s ? le1 : le0;
                if (t == lend) sret[(2*g + s) * HID + jown] = h;
            }
            asm volatile("bar.sync %0, 128;" :: "r"(g + 1) : "memory");
        }

        // fused FC: out[r] = W_fc @ h_ret + b_fc (threads 0..59 of group)
        if (u < VOCABN) {
            const float* wf = W_fc + u * HID;
#pragma unroll
            for (int s = 0; s < 2; s++) {
                const float* hh = sret + (2*g + s) * HID;
                float acc = b_fc[u];
#pragma unroll 8
                for (int k2 = 0; k2 < HID; k2++) acc += wf[k2] * hh[k2];
                out[(size_t)rows[2*k + s] * VOCABN + u] = acc;
            }
        }
    }
}

// ---------------- launch ----------------
extern "C" void kernel_launch(void* const* d_in, const int* in_sizes, int n_in,
                              void* d_out, int out_size) {
    const int*   x       = (const int*)d_in[0];
    const int*   lengths = (const int*)d_in[1];
    const float* emb     = (const float*)d_in[2];
    const float* W_ih    = (const float*)d_in[3];
    const float* W_hh    = (const float*)d_in[4];
    const float* W_fc    = (const float*)d_in[5];
    const float* b_fc    = (const float*)d_in[6];
    float*       out     = (float*)d_out;

    rnn_all<<<NCTA, 256>>>(x, lengths, W_hh, emb, W_ih, W_fc, b_fc, out);
}